// round 1
// baseline (speedup 1.0000x reference)
#include <cuda_runtime.h>
#include <cuda_bf16.h>
#include <math.h>

// Problem constants (fixed by the dataset's setup_inputs)
#define BB 16
#define PP 19248
#define CC 81
#define GG 16

#define VAR0 0.1f
#define VAR1 0.2f
#define POS_T 0.5f
#define NEG_T 0.4f
#define NPR   3
#define BBOX_ALPHA 1.5f

// ---------------- scratch (static device globals; no allocation) -------------
__device__ unsigned long long g_best_prior[BB * GG];   // packed (iou_bits<<32)|(~p)
__device__ float g_bt_over[BB * PP];
__device__ int   g_bt_idx [BB * PP];
__device__ float g_lossc  [BB * PP];
__device__ float g_sum_sl1[BB];
__device__ float g_sum_posce[BB];
__device__ float g_neg_sum[BB];
__device__ int   g_num_pos[BB];

// ---------------- helpers ----------------------------------------------------
__device__ __forceinline__ float warpMaxF(float v) {
    #pragma unroll
    for (int o = 16; o; o >>= 1) v = fmaxf(v, __shfl_xor_sync(0xFFFFFFFFu, v, o));
    return v;
}
__device__ __forceinline__ float warpSumF(float v) {
    #pragma unroll
    for (int o = 16; o; o >>= 1) v += __shfl_xor_sync(0xFFFFFFFFu, v, o);
    return v;
}

// ---------------- kernel 0: init scratch -------------------------------------
__global__ void k_init() {
    int t = threadIdx.x;
    if (t < BB * GG) g_best_prior[t] = 0ull;
    if (t < BB) {
        g_sum_sl1[t] = 0.f;
        g_sum_posce[t] = 0.f;
        g_neg_sum[t] = 0.f;
        g_num_pos[t] = 0;
    }
}

// ---------------- kernel 1: matching -----------------------------------------
// grid: (ceil(P/256), B), block 256
__global__ void k_match(const float* __restrict__ priors,
                        const float* __restrict__ gt_bboxes) {
    __shared__ float sgt[GG * 4];
    __shared__ unsigned long long sbest[GG];
    int b = blockIdx.y;
    int tid = threadIdx.x;
    if (tid < GG * 4) sgt[tid] = gt_bboxes[b * GG * 4 + tid];
    if (tid < GG) sbest[tid] = 0ull;
    __syncthreads();

    int p = blockIdx.x * blockDim.x + tid;
    if (p < PP) {
        const float4 pr = reinterpret_cast<const float4*>(priors)[b * PP + p];
        float px1 = pr.x - pr.z * 0.5f, py1 = pr.y - pr.w * 0.5f;
        float px2 = pr.x + pr.z * 0.5f, py2 = pr.y + pr.w * 0.5f;
        float pa = pr.z * pr.w;

        float bestv = -1.0f; int besti = 0;
        #pragma unroll
        for (int g = 0; g < GG; g++) {
            float gx1 = sgt[g * 4 + 0], gy1 = sgt[g * 4 + 1];
            float gx2 = sgt[g * 4 + 2], gy2 = sgt[g * 4 + 3];
            float iw = fminf(px2, gx2) - fmaxf(px1, gx1);
            float ih = fminf(py2, gy2) - fmaxf(py1, gy1);
            float inter = fmaxf(iw, 0.f) * fmaxf(ih, 0.f);
            float ga = (gx2 - gx1) * (gy2 - gy1);
            float iou = inter / fmaxf(pa + ga - inter, 1e-10f);
            if (iou > bestv) { bestv = iou; besti = g; }
            // pack for per-GT best-prior (ties -> smallest p, like jnp.argmax)
            unsigned long long key =
                (((unsigned long long)__float_as_uint(iou)) << 32) |
                (unsigned long long)(0xFFFFFFFFu - (unsigned)p);
            atomicMax(&sbest[g], key);
        }
        g_bt_over[b * PP + p] = bestv;
        g_bt_idx [b * PP + p] = besti;
    }
    __syncthreads();
    if (tid < GG) atomicMax(&g_best_prior[b * GG + tid], sbest[tid]);
}

// ---------------- kernel 2: force-match best priors (last write wins) --------
__global__ void k_force() {
    int b = threadIdx.x;
    if (b >= BB) return;
    for (int g = 0; g < GG; g++) {
        unsigned long long key = g_best_prior[b * GG + g];
        unsigned p = 0xFFFFFFFFu - (unsigned)(key & 0xFFFFFFFFull);
        g_bt_over[b * PP + p] = 2.0f;
        g_bt_idx [b * PP + p] = g;
    }
}

// ---------------- kernel 3: main fused pass (warp per prior) -----------------
// lse, loss_c candidate, positive CE + smooth-L1 accumulation
__global__ void k_main(const float* __restrict__ loc_data,
                       const float* __restrict__ conf_data,
                       const float* __restrict__ priors,
                       const float* __restrict__ gt_bboxes,
                       const int*   __restrict__ gt_labels) {
    int warp_id = blockIdx.x * (blockDim.x >> 5) + (threadIdx.x >> 5);
    int lane = threadIdx.x & 31;
    // warp_id in [0, B*P)
    int b = warp_id / PP;
    int p = warp_id - b * PP;
    long long base = ((long long)(b) * PP + p) * CC;

    // 81 classes: lane, lane+32, lane+64(<81 iff lane<17)
    float x0 = conf_data[base + lane];
    float x1 = conf_data[base + lane + 32];
    float x2 = (lane < 17) ? conf_data[base + lane + 64] : -INFINITY;

    float m = fmaxf(fmaxf(x0, x1), x2);
    m = warpMaxF(m);
    float s = expf(x0 - m) + expf(x1 - m) + ((lane < 17) ? expf(x2 - m) : 0.f);
    s = warpSumF(s);
    float lse = m + logf(s);
    float conf0 = __shfl_sync(0xFFFFFFFFu, x0, 0);

    float over = g_bt_over[b * PP + p];
    int   bidx = g_bt_idx [b * PP + p];

    int ct;
    if (over < NEG_T)      ct = 0;
    else if (over < POS_T) ct = -1;
    else                   ct = gt_labels[b * GG + bidx];

    if (lane == 0)
        g_lossc[b * PP + p] = (ct == 0) ? (lse - conf0) : 0.f;

    if (ct > 0) {
        int tgt = ct;
        float vt = ((lane == tgt) ? x0 : 0.f) +
                   ((lane + 32 == tgt) ? x1 : 0.f) +
                   ((lane < 17 && lane + 64 == tgt) ? x2 : 0.f);
        vt = warpSumF(vt);
        if (lane == 0) {
            float ce = lse - vt;
            // encode + smooth L1
            float4 pr = reinterpret_cast<const float4*>(priors)[b * PP + p];
            float4 gb = reinterpret_cast<const float4*>(gt_bboxes)[b * GG + bidx];
            float4 ld = reinterpret_cast<const float4*>(loc_data)[b * PP + p];
            float gcx = ((gb.x + gb.z) * 0.5f - pr.x) / (VAR0 * pr.z);
            float gcy = ((gb.y + gb.w) * 0.5f - pr.y) / (VAR0 * pr.w);
            float gw  = logf(fmaxf((gb.z - gb.x) / pr.z, 1e-8f)) / VAR1;
            float gh  = logf(fmaxf((gb.w - gb.y) / pr.w, 1e-8f)) / VAR1;
            float d0 = ld.x - gcx, d1 = ld.y - gcy, d2 = ld.z - gw, d3 = ld.w - gh;
            float sl1 = 0.f;
            float a;
            a = fabsf(d0); sl1 += (a < 1.f) ? 0.5f * d0 * d0 : a - 0.5f;
            a = fabsf(d1); sl1 += (a < 1.f) ? 0.5f * d1 * d1 : a - 0.5f;
            a = fabsf(d2); sl1 += (a < 1.f) ? 0.5f * d2 * d2 : a - 0.5f;
            a = fabsf(d3); sl1 += (a < 1.f) ? 0.5f * d3 * d3 : a - 0.5f;
            atomicAdd(&g_sum_sl1[b], sl1);
            atomicAdd(&g_sum_posce[b], ce);
            atomicAdd(&g_num_pos[b], 1);
        }
    }
}

// ---------------- kernel 4: OHEM selection (k-th largest via radix histo) ----
// one block per image, 512 threads
__global__ void k_select() {
    __shared__ unsigned int hist[2048];
    __shared__ unsigned int sh_prefix, sh_mask;
    __shared__ int sh_krem, sh_k;
    __shared__ float sh_sum;
    __shared__ int sh_cnt;
    int b = blockIdx.x;
    int tid = threadIdx.x;
    const float* v = &g_lossc[b * PP];

    if (tid == 0) {
        int np = g_num_pos[b];
        int k = NPR * np;
        if (k > PP - 1) k = PP - 1;
        if (k < 0) k = 0;
        sh_k = k; sh_krem = k;
        sh_prefix = 0u; sh_mask = 0u;
        sh_sum = 0.f; sh_cnt = 0;
    }
    __syncthreads();
    if (sh_k <= 0) {
        if (tid == 0) g_neg_sum[b] = 0.f;
        return;
    }

    const int shifts[3] = {21, 10, 0};
    const int nbins[3]  = {2048, 2048, 1024};
    for (int lvl = 0; lvl < 3; lvl++) {
        int sft = shifts[lvl], nb = nbins[lvl];
        for (int i = tid; i < nb; i += blockDim.x) hist[i] = 0u;
        __syncthreads();
        unsigned pref = sh_prefix, msk = sh_mask;
        for (int i = tid; i < PP; i += blockDim.x) {
            unsigned u = __float_as_uint(v[i]);  // all values >= 0: bit order = value order
            if ((u & msk) == pref)
                atomicAdd(&hist[(u >> sft) & (nb - 1)], 1u);
        }
        __syncthreads();
        if (tid == 0) {
            int krem = sh_krem;
            int cum = 0, cut = 0;
            for (int bin = nb - 1; bin >= 0; bin--) {
                cum += (int)hist[bin];
                if (cum >= krem) { cut = bin; break; }
            }
            sh_krem = krem - (cum - (int)hist[cut]);
            sh_prefix = sh_prefix | ((unsigned)cut << sft);
            sh_mask = sh_mask | ((unsigned)(nb - 1) << sft);
        }
        __syncthreads();
    }

    unsigned Tbits = sh_prefix;       // exact k-th largest value's bits
    float T = __uint_as_float(Tbits);
    float lsum = 0.f; int lcnt = 0;
    for (int i = tid; i < PP; i += blockDim.x) {
        float x = v[i];
        if (__float_as_uint(x) > Tbits) { lsum += x; lcnt++; }
    }
    // block reduce
    lsum = warpSumF(lsum);
    lcnt = (int)warpSumF((float)lcnt);
    if ((tid & 31) == 0) { atomicAdd(&sh_sum, lsum); atomicAdd(&sh_cnt, lcnt); }
    __syncthreads();
    if (tid == 0) {
        // ties at T contribute T each regardless of stable-rank order
        g_neg_sum[b] = sh_sum + (float)(sh_k - sh_cnt) * T;
    }
}

// ---------------- kernel 5: finalize -----------------------------------------
__global__ void k_final(float* __restrict__ out) {
    if (threadIdx.x == 0) {
        float lossB = 0.f, lossC = 0.f;
        for (int b = 0; b < BB; b++) {
            int np = g_num_pos[b];
            float denom = (float)max(np, 1);
            lossB += g_sum_sl1[b] / denom;
            lossC += g_sum_posce[b] + g_neg_sum[b];
        }
        out[0] = lossB * BBOX_ALPHA / (float)BB;
        out[1] = lossC / (float)BB;
    }
}

// ---------------- launch ------------------------------------------------------
extern "C" void kernel_launch(void* const* d_in, const int* in_sizes, int n_in,
                              void* d_out, int out_size) {
    const float* loc_data  = (const float*)d_in[0];
    const float* conf_data = (const float*)d_in[1];
    const float* priors    = (const float*)d_in[2];
    const float* gt_bboxes = (const float*)d_in[3];
    const int*   gt_labels = (const int*)d_in[4];
    float* out = (float*)d_out;

    k_init<<<1, 256>>>();
    dim3 mg((PP + 255) / 256, BB);
    k_match<<<mg, 256>>>(priors, gt_bboxes);
    k_force<<<1, BB>>>();
    int nwarps = BB * PP;                 // 307968, divisible by 8
    k_main<<<nwarps / 8, 256>>>(loc_data, conf_data, priors, gt_bboxes, gt_labels);
    k_select<<<BB, 512>>>();
    k_final<<<1, 32>>>(out);
}